// round 9
// baseline (speedup 1.0000x reference)
#include <cuda_runtime.h>
#include <cstdint>

// minGRU bidirectional scan. R9 = R8 + chunked-arrival TMA pipelining:
// input is loaded as 4 quarter-chunks (h+g, 16KB each, own mbarrier); compute
// starts on quarter 0 as soon as it lands, overlapping the remaining DMA.
// x: [B, 512, L] fp32 -> out: [B, 256, L] fp32.
//   out channel c2 (0..255): rev = c2>=128, c = c2&127
//   h row = x[b, (rev?256:0)+c, :], gate row = h row + 128 channels.
// Recurrence (logical order; rev scans t = L-1..0):
//   out_t = a_t*out_{t-1} + b_t,  a = 1/(1+e^gate), b = (1-a)*g(h),
//   g(v) = v>=0 ? 1+v : e^v.
//
// Thread t owns 4 chunks of 4 logical elems, one per quarter:
//   Q_q = [q*L/4 + 4t, q*L/4 + 4t + 4)  ->  float4 index q*L/16 + t
// (rev: logical quarter q lives in physical quarter 3-q).

constexpr int L  = 8192;
constexpr int NT = 512;
constexpr int NW = NT / 32;     // 16 warps
constexpr int QF = L / 16;      // float4s per quarter = 512
constexpr int QE = L / 4;       // elements per quarter = 2048
constexpr int QB = QE * 4;      // bytes per quarter row chunk = 8192

// dynamic smem: hbuf[L] | gbuf[L] | mbar[4]
constexpr int SMEM_BYTES = 2 * L * 4 + 4 * 8;

__device__ __forceinline__ float fast_rcp(float v) {
    float r;
    asm("rcp.approx.f32 %0, %1;" : "=f"(r) : "f"(v));
    return r;
}

__device__ __forceinline__ void mbar_wait_parity0(uint32_t mbar) {
    uint32_t done;
    asm volatile(
        "{\n\t.reg .pred p;\n\t"
        "mbarrier.try_wait.parity.shared::cta.b64 p, [%1], 0;\n\t"
        "selp.b32 %0, 1, 0, p;\n\t}"
        : "=r"(done) : "r"(mbar) : "memory");
    while (!done) {
        asm volatile(
            "{\n\t.reg .pred p;\n\t"
            "mbarrier.try_wait.parity.shared::cta.b64 p, [%1], 0, 0x989680;\n\t"
            "selp.b32 %0, 1, 0, p;\n\t}"
            : "=r"(done) : "r"(mbar) : "memory");
    }
}

__global__ __launch_bounds__(NT, 2)
void mingru_bidir_kernel(const float* __restrict__ x, float* __restrict__ out) {
    extern __shared__ float smem[];
    float* hbuf = smem;
    float* gbuf = smem + L;
    uint64_t* mbar64 = (uint64_t*)(smem + 2 * L);

    __shared__ float sA[4][NW], sB[4][NW], sT[8];

    const int blk = blockIdx.x;
    const int b   = blk >> 8;
    const int c2  = blk & 255;
    const bool rev = (c2 & 128) != 0;
    const int hch = ((c2 & 128) ? 256 : 0) + (c2 & 127);

    const float* hrow = x + (size_t)(b * 512 + hch) * L;
    const float* grow = hrow + (size_t)128 * L;
    float4* __restrict__ o4 = (float4*)(out + (size_t)(b * 256 + c2) * L);

    const int tid  = threadIdx.x;
    const int lane = tid & 31;
    const int warp = tid >> 5;

    const uint32_t mbar_u32 = (uint32_t)__cvta_generic_to_shared(mbar64);
    const uint32_t hbuf_u32 = (uint32_t)__cvta_generic_to_shared(hbuf);
    const uint32_t gbuf_u32 = (uint32_t)__cvta_generic_to_shared(gbuf);

    // ---- issue 4 chunked loads (first-needed physical quarter first) ----
    if (tid == 0) {
        #pragma unroll
        for (int i = 0; i < 4; ++i) {
            const int p = rev ? (3 - i) : i;      // physical quarter, logical order
            asm volatile("mbarrier.init.shared.b64 [%0], 1;"
                         :: "r"(mbar_u32 + 8 * p) : "memory");
            asm volatile("mbarrier.arrive.expect_tx.shared.b64 _, [%0], %1;"
                         :: "r"(mbar_u32 + 8 * p), "r"(2 * QB) : "memory");
            asm volatile("cp.async.bulk.shared::cta.global.mbarrier::complete_tx::bytes "
                         "[%0], [%1], %2, [%3];"
                         :: "r"(hbuf_u32 + p * QB), "l"(hrow + p * QE),
                            "r"(QB), "r"(mbar_u32 + 8 * p) : "memory");
            asm volatile("cp.async.bulk.shared::cta.global.mbarrier::complete_tx::bytes "
                         "[%0], [%1], %2, [%3];"
                         :: "r"(gbuf_u32 + p * QB), "l"(grow + p * QE),
                            "r"(QB), "r"(mbar_u32 + 8 * p) : "memory");
        }
    }
    __syncthreads();   // mbarrier inits visible before any try_wait

    const float4* h4 = (const float4*)hbuf;
    const float4* g4 = (const float4*)gbuf;

    // float4 index for logical quarter q (smem load AND global store)
    int fidx[4];
    #pragma unroll
    for (int q = 0; q < 4; ++q)
        fidx[q] = rev ? (L / 4 - 1 - (q * QF + tid)) : (q * QF + tid);

    // ---- Phase 1: consume quarters as they arrive ----
    float av[16], bv[16];
    float Aq[4], Bq[4];
    #pragma unroll
    for (int q = 0; q < 4; ++q) {
        const int p = rev ? (3 - q) : q;          // physical quarter holding logical q
        mbar_wait_parity0(mbar_u32 + 8 * p);

        float4 hv = h4[fidx[q]];
        float4 gv = g4[fidx[q]];
        if (rev) {
            hv = make_float4(hv.w, hv.z, hv.y, hv.x);
            gv = make_float4(gv.w, gv.z, gv.y, gv.x);
        }
        const float hh[4] = {hv.x, hv.y, hv.z, hv.w};
        const float gg[4] = {gv.x, gv.y, gv.z, gv.w};
        float A = 1.0f, B = 0.0f;
        #pragma unroll
        for (int k = 0; k < 4; ++k) {
            const int j = q * 4 + k;
            const float a  = fast_rcp(1.0f + __expf(gg[k]));
            const float gh = (hh[k] >= 0.0f) ? (1.0f + hh[k]) : __expf(hh[k]);
            const float bb = (1.0f - a) * gh;
            av[j] = a;
            bv[j] = bb;
            B = fmaf(B, a, bb);
            A *= a;
        }
        Aq[q] = A;
        Bq[q] = B;
    }

    // ---- Phase 2: 4 interleaved warp scans (all shfl at full-warp scope) ----
    #pragma unroll
    for (int off = 1; off < 32; off <<= 1) {
        #pragma unroll
        for (int q = 0; q < 4; ++q) {
            const float Au = __shfl_up_sync(0xFFFFFFFFu, Aq[q], off);
            const float Bu = __shfl_up_sync(0xFFFFFFFFu, Bq[q], off);
            if (lane >= off) {
                Bq[q] = fmaf(Bu, Aq[q], Bq[q]);
                Aq[q] *= Au;
            }
        }
    }
    float Ae[4], Be[4];
    #pragma unroll
    for (int q = 0; q < 4; ++q) {
        Ae[q] = __shfl_up_sync(0xFFFFFFFFu, Aq[q], 1);
        Be[q] = __shfl_up_sync(0xFFFFFFFFu, Bq[q], 1);
        if (lane == 0) { Ae[q] = 1.0f; Be[q] = 0.0f; }
        if (lane == 31) { sA[q][warp] = Aq[q]; sB[q][warp] = Bq[q]; }
    }
    __syncthreads();

    // warp 0: block scan over 16 warp totals, 4 quarters interleaved
    if (warp == 0) {
        float wa[4], wb[4];
        #pragma unroll
        for (int q = 0; q < 4; ++q) {
            wa[q] = sA[q][lane & (NW - 1)];
            wb[q] = sB[q][lane & (NW - 1)];
        }
        #pragma unroll
        for (int off = 1; off < NW; off <<= 1) {
            #pragma unroll
            for (int q = 0; q < 4; ++q) {
                const float Au = __shfl_up_sync(0xFFFFFFFFu, wa[q], off);
                const float Bu = __shfl_up_sync(0xFFFFFFFFu, wb[q], off);
                if (lane >= off) {
                    wb[q] = fmaf(Bu, wa[q], wb[q]);
                    wa[q] *= Au;
                }
            }
        }
        #pragma unroll
        for (int q = 0; q < 4; ++q) {
            const float wae = __shfl_up_sync(0xFFFFFFFFu, wa[q], 1);   // full warp
            const float wbe = __shfl_up_sync(0xFFFFFFFFu, wb[q], 1);   // full warp
            if (lane < NW) {
                sA[q][lane] = (lane == 0) ? 1.0f : wae;
                sB[q][lane] = (lane == 0) ? 0.0f : wbe;
            }
            if (lane == NW - 1) { sT[q] = wa[q]; sT[4 + q] = wb[q]; }
        }
    }
    __syncthreads();

    // quarter seeds: s0 = 0, s_{q+1} = At_q * s_q + Bt_q
    float seed[4];
    seed[0] = 0.0f;
    seed[1] = sT[4];
    seed[2] = fmaf(sT[1], seed[1], sT[5]);
    seed[3] = fmaf(sT[2], seed[2], sT[6]);

    // ---- Phase 3: replay + direct coalesced STG.128 (per quarter) ----
    #pragma unroll
    for (int q = 0; q < 4; ++q) {
        float s = fmaf(Ae[q], fmaf(sA[q][warp], seed[q], sB[q][warp]), Be[q]);
        float o[4];
        #pragma unroll
        for (int k = 0; k < 4; ++k) {
            s = fmaf(av[q * 4 + k], s, bv[q * 4 + k]);
            o[k] = s;
        }
        o4[fidx[q]] = rev ? make_float4(o[3], o[2], o[1], o[0])
                          : make_float4(o[0], o[1], o[2], o[3]);
    }
}

extern "C" void kernel_launch(void* const* d_in, const int* in_sizes, int n_in,
                              void* d_out, int out_size) {
    const float* x = (const float*)d_in[0];
    float* out = (float*)d_out;
    const int B = in_sizes[0] / (512 * L);
    cudaFuncSetAttribute(mingru_bidir_kernel,
                         cudaFuncAttributeMaxDynamicSharedMemorySize, SMEM_BYTES);
    mingru_bidir_kernel<<<B * 256, NT, SMEM_BYTES>>>(x, out);
}